// round 17
// baseline (speedup 1.0000x reference)
#include <cuda_runtime.h>
#include <cuda.h>
#include <cuda_fp16.h>
#include <math.h>
#include <stdint.h>

#define DM 1024
#define NH 16
#define HD 64
#define MSL 5000
#define BB 2
#define SS 2048
#define MT (BB*SS)   // 4096 rows total

// Scratch (allocation-free rule: device globals), all fp16
__device__ __half g_a[MT*DM];         // GEMM A operand (xpe, later attention O)
__device__ __half g_w[4*DM*DM];       // stacked Wq|Wk|Wv|Wo (single fp16)
// Q/K/V in [B,H,S,hd]; Q pre-scaled by log2(e)/32; all single fp16
__device__ __half g_qh[MT*DM];
__device__ __half g_kh[MT*DM];
__device__ __half g_vh[MT*DM];

// ---------------------------------------------------------------------------
// helpers
// ---------------------------------------------------------------------------
__device__ __forceinline__ uint32_t smem_u32(const void* p) {
    uint32_t a;
    asm("{ .reg .u64 t; cvta.to.shared.u64 t, %1; cvt.u32.u64 %0, t; }" : "=r"(a) : "l"(p));
    return a;
}

#define MBAR_INIT(addr, cnt) \
    asm volatile("mbarrier.init.shared.b64 [%0], %1;" :: "r"(addr), "r"(cnt) : "memory")

#define EXPECT_TX(addr, bytes) \
    asm volatile("mbarrier.arrive.expect_tx.shared.b64 _, [%0], %1;" :: "r"(addr), "r"(bytes) : "memory")

#define TMA2D(smem, mapp, x, y, mbar) \
    asm volatile("cp.async.bulk.tensor.2d.shared::cluster.global.tile.mbarrier::complete_tx::bytes " \
        "[%0], [%1, {%2, %3}], [%4];" \
        :: "r"(smem), "l"(mapp), "r"(x), "r"(y), "r"(mbar) : "memory")

__device__ __forceinline__ void mbar_wait(uint32_t addr, uint32_t parity) {
    uint32_t done;
    asm volatile(
        "{\n\t.reg .pred p;\n\t"
        "mbarrier.try_wait.parity.shared.b64 p, [%1], %2;\n\t"
        "selp.b32 %0,1,0,p;\n\t}"
        : "=r"(done) : "r"(addr), "r"(parity) : "memory");
    while (!done) {
        asm volatile(
            "{\n\t.reg .pred p;\n\t"
            "mbarrier.try_wait.parity.shared.b64 p, [%1], %2, 0x989680;\n\t"
            "selp.b32 %0,1,0,p;\n\t}"
            : "=r"(done) : "r"(addr), "r"(parity) : "memory");
    }
}

#define LDSM4(r, addr) \
    asm volatile("ldmatrix.sync.aligned.m8n8.x4.shared.b16 {%0,%1,%2,%3}, [%4];" \
        : "=r"((r)[0]), "=r"((r)[1]), "=r"((r)[2]), "=r"((r)[3]) : "r"(addr))

#define LDSM4T(r, addr) \
    asm volatile("ldmatrix.sync.aligned.m8n8.x4.trans.shared.b16 {%0,%1,%2,%3}, [%4];" \
        : "=r"((r)[0]), "=r"((r)[1]), "=r"((r)[2]), "=r"((r)[3]) : "r"(addr))

// fp16 MMA
#define MMA16816H(d, a, b0v, b1v) \
    asm volatile("mma.sync.aligned.m16n8k16.row.col.f32.f16.f16.f32 " \
        "{%0,%1,%2,%3}, {%4,%5,%6,%7}, {%8,%9}, {%0,%1,%2,%3};" \
        : "+f"((d)[0]), "+f"((d)[1]), "+f"((d)[2]), "+f"((d)[3]) \
        : "r"((a)[0]), "r"((a)[1]), "r"((a)[2]), "r"((a)[3]), "r"(b0v), "r"(b1v))

__device__ __forceinline__ uint32_t pack_h(float hi, float lo) {
    __half2 h = __floats2half2_rn(lo, hi);   // lo -> low half, hi -> high half
    return *reinterpret_cast<uint32_t*>(&h);
}
__device__ __forceinline__ float ex2(float x) {
    float r;
    asm("ex2.approx.ftz.f32 %0, %1;" : "=f"(r) : "f"(x));
    return r;
}

// ---------------------------------------------------------------------------
// Kernel 1: fused PE:  (x + a*sin_pe + (1-a)*rel) -> g_a (fp16)
// ---------------------------------------------------------------------------
__global__ void pe_kernel(const float* __restrict__ x,
                          const float* __restrict__ rel,
                          const float* __restrict__ alphap) {
    int idx = blockIdx.x*blockDim.x + threadIdx.x;
    if (idx >= MT*(DM/2)) return;
    int m  = idx >> 9;
    int pp = idx & 511;
    int s  = m & (SS-1);
    float a = alphap[0];
    float freq = __expf(-(float)(2*pp) * (9.210340371976184f/(float)DM));
    float ang = (float)s * freq;
    float sn, cs;
    sincosf(ang, &sn, &cs);
    const float* rr = rel + (size_t)(MSL - SS + s)*DM + 2*pp;
    float2 xv = *(const float2*)(x + (size_t)idx*2);
    float om = 1.0f - a;
    float ox = xv.x + a*sn + om*rr[0];
    float oy = xv.y + a*cs + om*rr[1];
    *(__half2*)(g_a + (size_t)idx*2) = __floats2half2_rn(ox, oy);
}

// ---------------------------------------------------------------------------
// Kernel 2: all four weight matrices -> fp16 in one launch.
// ---------------------------------------------------------------------------
#define NW4 (DM*DM/4)   // 262144 float4 per matrix
__global__ void conv4_kernel(const float* __restrict__ w0,
                             const float* __restrict__ w1,
                             const float* __restrict__ w2,
                             const float* __restrict__ w3) {
    int i = blockIdx.x*blockDim.x + threadIdx.x;
    if (i >= 4*NW4) return;
    const int which = i >> 18;            // NW4 = 2^18
    const int j = i & (NW4 - 1);
    const float* src = (which == 0) ? w0 : (which == 1) ? w1 : (which == 2) ? w2 : w3;
    float4 v = ((const float4*)src)[j];
    size_t o = (size_t)which*DM*DM + (size_t)j*4;
    __half2* hp = (__half2*)(g_w + o);
    hp[0] = __floats2half2_rn(v.x, v.y);
    hp[1] = __floats2half2_rn(v.z, v.w);
}

// ---------------------------------------------------------------------------
// TMA fp16 GEMM: C = A W^T + bias. Block 128x64, 128 threads,
// warp tile 64x32. K-chunk 64, 2-stage TMA, 3 CTAs/SM. (unchanged)
// ---------------------------------------------------------------------------
#define GA 16384                  // A tile: 128 rows x 128B (SW128)
#define GW 8192                   // W tile: 64 rows x 128B
#define GSTG (GA + GW)            // A W = 24576
#define GEMM_SMEM (2*GSTG + 1088) // 50240 -> 3 CTAs/SM

#define QSCALE 0.04508422002778f  // log2(e)/32
#define SMAX   16.0f              // fixed softmax stabilizer (log2 domain)

__global__ void __launch_bounds__(128, 3) gemm_tma(
    const __grid_constant__ CUtensorMap mA,
    const __grid_constant__ CUtensorMap mW,
    const float* __restrict__ b0, const float* __restrict__ b1,
    const float* __restrict__ b2, float* __restrict__ outp,
    int wbase, int mode)
{
    extern __shared__ char smem[];
    const uint32_t sb = (smem_u32(smem) + 1023) & ~1023u;
    const uint32_t mb = sb + 2*GSTG;
    const int t  = threadIdx.x;
    const int m0 = blockIdx.y * 128;
    const int n0 = blockIdx.x * 64;

    if (t == 0) { MBAR_INIT(mb, 1); MBAR_INIT(mb + 8, 1); }
    __syncthreads();

    auto issue = [&](int ck) {
        const uint32_t d   = sb + (uint32_t)(ck & 1) * GSTG;
        const uint32_t bar = mb + (uint32_t)(ck & 1) * 8;
        EXPECT_TX(bar, (uint32_t)GSTG);
        TMA2D(d + 0,  &mA, ck*64, m0, bar);
        TMA2D(d + GA, &mW, ck*64, wbase + n0, bar);
    };
    if (t == 0) { issue(0); issue(1); }

    const int wid = t >> 5, l = t & 31;
    const int warpM = wid & 1;
    const int warpN = wid >> 1;          // 0..1
    const int q  = l >> 3, lr = l & 7;

    float acc[16][4];
    #pragma unroll
    for (int i = 0; i < 16; i++)
        #pragma unroll
        for (int j = 0; j < 4; j++) acc[i][j] = 0.f;

    uint32_t arow[4], brow[2];
    #pragma unroll
    for (int mt = 0; mt < 4; mt++) arow[mt] = (uint32_t)(warpM*64 + mt*16 + (q & 1)*8 + lr) * 128;
    #pragma unroll
    for (int np = 0; np < 2; np++) brow[np] = (uint32_t)(warpN*32 + np*16 + (q >> 1)*8 + lr) * 128;
    uint32_t axc[4], bxc[4];
    #pragma unroll
    for (int s = 0; s < 4; s++) {
        axc[s] = (uint32_t)((((q >> 1) + 2*s) ^ lr) * 16);
        bxc[s] = (uint32_t)((((q & 1) + 2*s) ^ lr) * 16);
    }

    int ph0 = 0, ph1 = 0;
    for (int ch = 0; ch < DM/64; ch++) {
        const int bsel = ch & 1;
        if (bsel == 0) { mbar_wait(mb,     (uint32_t)ph0); ph0 ^= 1; }
        else           { mbar_wait(mb + 8, (uint32_t)ph1); ph1 ^= 1; }
        const uint32_t bs = sb + (uint32_t)bsel * GSTG;

        #pragma unroll
        for (int s = 0; s < 4; s++) {
            uint32_t ah[4][4];
            #pragma unroll
            for (int mt = 0; mt < 4; mt++)
                LDSM4(ah[mt], bs + arow[mt] + axc[s]);
            uint32_t bh[2][4];
            #pragma unroll
            for (int np = 0; np < 2; np++)
                LDSM4(bh[np], bs + GA + brow[np] + bxc[s]);
            #pragma unroll
            for (int mt = 0; mt < 4; mt++)
                #pragma unroll
                for (int nt = 0; nt < 4; nt++) {
                    const int np = nt >> 1, h = (nt & 1) * 2;
                    MMA16816H(acc[mt*4+nt], ah[mt], bh[np][h], bh[np][h+1]);
                }
        }
        __syncthreads();
        if (t == 0 && ch + 2 < DM/64) issue(ch + 2);
    }

    // epilogue
    if (mode == 0) {
        const int which = n0 >> 10;
        const float* bias = (which == 0) ? b0 : (which == 1) ? b1 : b2;
        __half* dst = (which == 0) ? g_qh : (which == 1) ? g_kh : g_vh;
        const float scl = (which == 0) ? QSCALE : 1.0f;
        const int nloc0 = n0 & 1023;
        #pragma unroll
        for (int nt = 0; nt < 4; nt++) {
            const int n = nloc0 + warpN*32 + nt*8 + (l & 3)*2;
            const float bx = bias[n], by = bias[n+1];
            #pragma unroll
            for (int mt = 0; mt < 4; mt++) {
                const float* d = acc[mt*4 + nt];
                #pragma unroll
                for (int half = 0; half < 2; half++) {
                    const int m = m0 + warpM*64 + mt*16 + (l >> 2) + half*8;
                    float vx = (d[half*2 + 0] + bx) * scl;
                    float vy = (d[half*2 + 1] + by) * scl;
                    const int bb = m >> 11, s = m & (SS-1);
                    const int hh = n >> 6, dd = n & 63;
                    size_t o = (size_t)((bb*NH + hh)*SS + s)*HD + dd;
                    *(__half2*)(dst + o) = __floats2half2_rn(vx, vy);
                }
            }
        }
    } else {
        #pragma unroll
        for (int nt = 0; nt < 4; nt++) {
            const int n = n0 + warpN*32 + nt*8 + (l & 3)*2;
            const float bx = b0[n], by = b0[n+1];
            #pragma unroll
            for (int mt = 0; mt < 4; mt++) {
                const float* d = acc[mt*4 + nt];
                #pragma unroll
                for (int half = 0; half < 2; half++) {
                    const int m = m0 + warpM*64 + mt*16 + (l >> 2) + half*8;
                    float2 v;
                    v.x = d[half*2 + 0] + bx;
                    v.y = d[half*2 + 1] + by;
                    *(float2*)&outp[(size_t)m*DM + n] = v;
                }
            }
        }
    }
}

// ---------------------------------------------------------------------------
// Flash attention, fp16, fixed-max softmax, 2M x 2N warp split.
// Block: 64 queries x one (b,h); 128 threads = 4 warps:
//   warpM = wid&1 -> q rows [32*warpM, +32); warpN = wid>>1 -> kv cols [32*warpN, +32).
// K/V smem reads replicated only 2x (was 4x). Partial O/lsum merged across
// the two N-warps once at the end via smem (reusing KV buffers).
// KV tile 64, double-buffered TMA (SW128), 3 CTAs/SM.
// ---------------------------------------------------------------------------
#define FQB 8192                  // Q tile: 64 rows x 128B
#define FKB 8192                  // KV array tile: 64 rows x 128B
#define FSTG (2*FKB)              // KH VH = 16384
#define FL_SMEM (FQB + 2*FSTG + 1088)   // 42048 -> 3 CTAs/SM
#define ORS 72                    // epilogue scratch row stride (floats)

__global__ void __launch_bounds__(128, 3) flash_tma(
    const __grid_constant__ CUtensorMap mQh,
    const __grid_constant__ CUtensorMap mKh,
    const __grid_constant__ CUtensorMap mVh)
{
    extern __shared__ char fsm[];
    const uint32_t base = smem_u32(fsm);
    const uint32_t sb   = (base + 1023) & ~1023u;
    char* fb = fsm + (sb - base);        // aligned C pointer mirror of sb
    const uint32_t kvb = sb + FQB;
    const uint32_t mbq = sb + FQB + 2*FSTG;
    const int bh = blockIdx.y;
    const int q0 = blockIdx.x * 64;
    const int row0 = bh * SS;
    const int t = threadIdx.x, wid = t >> 5, l = t & 31;
    const int q = l >> 3, lr = l & 7;
    const int warpM = wid & 1;           // q half
    const int warpN = wid >> 1;          // kv half
    const int wq0 = warpM * 32;
    const int wn0 = warpN * 32;

    if (t == 0) { MBAR_INIT(mbq, 1); MBAR_INIT(mbq + 8, 1); MBAR_INIT(mbq + 16, 1); }
    __syncthreads();

    auto kvissue = [&](int ti) {
        const uint32_t d   = kvb + (uint32_t)(ti & 1) * FSTG;
        const uint32_t bar = mbq + 8 + (uint32_t)(ti & 1) * 8;
        EXPECT_TX(bar, (uint32_t)FSTG);
        const int y = row0 + ti*64;
        TMA2D(d + 0*FKB, &mKh, 0, y, bar);
        TMA2D(d + 1*FKB, &mVh, 0, y, bar);
    };
    if (t == 0) {
        EXPECT_TX(mbq, (uint32_t)FQB);
        TMA2D(sb, &mQh, 0, row0 + q0, mbq);
        kvissue(0);
        kvissue(1);
    }

    mbar_wait(mbq, 0);

    // Q fragments (persistent): mt in {0,1} -> rows wq0 + mt*16
    uint32_t qhf[2][4][4];
    #pragma unroll
    for (int mt = 0; mt < 2; mt++) {
        const uint32_t qrow = (uint32_t)(wq0 + mt*16 + (q & 1)*8 + lr) * 128;
        #pragma unroll
        for (int kt = 0; kt < 4; kt++) {
            const uint32_t c = (uint32_t)((((q >> 1) + 2*kt) ^ lr) * 16);
            LDSM4(qhf[mt][kt], sb + qrow + c);
        }
    }

    uint32_t krow[2], vrow[2], kxc[4], vxc[4];
    #pragma unroll
    for (int np = 0; np < 2; np++) krow[np] = (uint32_t)(wn0 + np*16 + (q >> 1)*8 + lr) * 128;
    #pragma unroll
    for (int kp = 0; kp < 2; kp++) vrow[kp] = (uint32_t)(wn0 + kp*16 + (q & 1)*8 + lr) * 128;
    #pragma unroll
    for (int kt = 0; kt < 4; kt++) kxc[kt] = (uint32_t)((((q & 1) + 2*kt) ^ lr) * 16);
    #pragma unroll
    for (int g = 0; g < 4; g++)  vxc[g]  = (uint32_t)(((2*g + (q >> 1)) ^ lr) * 16);

    float oacc[16][4];                    // [mt*8 + nj][4]
    #pragma unroll
    for (int i = 0; i < 16; i++)
        #pragma unroll
        for (int j = 0; j < 4; j++) oacc[i][j] = 0.f;
    float lsum[2][2] = {{0.f, 0.f}, {0.f, 0.f}};   // [mt][row-half]

    int kvph0 = 0, kvph1 = 0;
    for (int ti = 0; ti < SS/64; ti++) {
        const int bsel = ti & 1;
        if (bsel == 0) { mbar_wait(mbq + 8,  (uint32_t)kvph0); kvph0 ^= 1; }
        else           { mbar_wait(mbq + 16, (uint32_t)kvph1); kvph1 ^= 1; }
        const uint32_t kb = kvb + (uint32_t)bsel * FSTG;

        // S[32q x 32kv] = Q K^T  (sacc[mt*4 + nt])
        float sacc[8][4];
        #pragma unroll
        for (int i = 0; i < 8; i++)
            #pragma unroll
            for (int j = 0; j < 4; j++) sacc[i][j] = 0.f;

        #pragma unroll
        for (int kt = 0; kt < 4; kt++) {
            uint32_t khf[2][4];
            #pragma unroll
            for (int np = 0; np < 2; np++)
                LDSM4(khf[np], kb + krow[np] + kxc[kt]);
            #pragma unroll
            for (int mt = 0; mt < 2; mt++)
                #pragma unroll
                for (int nt = 0; nt < 4; nt++) {
                    const int np = nt >> 1, h = (nt & 1)*2;
                    MMA16816H(sacc[mt*4+nt], qhf[mt][kt], khf[np][h], khf[np][h+1]);
                }
        }

        // fixed-max softmax weights: P = exp2(s - SMAX)
        #pragma unroll
        for (int mt = 0; mt < 2; mt++)
            #pragma unroll
            for (int nt = 0; nt < 4; nt++) {
                float* s = sacc[mt*4+nt];
                s[0] = ex2(s[0] - SMAX);
                s[1] = ex2(s[1] - SMAX);
                s[2] = ex2(s[2] - SMAX);
                s[3] = ex2(s[3] - SMAX);
                lsum[mt][0] += s[0] + s[1];
                lsum[mt][1] += s[2] + s[3];
            }

        // O += P V  (V rows = this warp's 32 kv)
        #pragma unroll
        for (int kp = 0; kp < 2; kp++) {
            uint32_t vhf[4][4];
            #pragma unroll
            for (int g = 0; g < 4; g++)
                LDSM4T(vhf[g], kb + FKB + vrow[kp] + vxc[g]);
            #pragma unroll
            for (int mt = 0; mt < 2; mt++) {
                uint32_t ph[4];
                #pragma unroll
                for (int e = 0; e < 4; e++) {
                    const float* s0 = sacc[mt*4 + 2*kp + (e >> 1)];
                    ph[e] = pack_h(s0[(e & 1)*2 + 1], s0[(e & 1)*2]);
                }
                #pragma unroll
                for (int nj = 0; nj < 8; nj++) {
                    const int g = nj >> 1, o = (nj & 1)*2;
                    MMA16816H(oacc[mt*8+nj], ph, vhf[g][o], vhf[g][o+1]);
                }
            }
        }

        __syncthreads();
        if (t == 0 && ti + 2 < SS/64) kvissue(ti + 2);
    }

    // ---- merge partial O / lsum across the two N-warps ----
    // reduce lsum over the 4 lanes sharing each row
    #pragma unroll
    for (int mt = 0; mt < 2; mt++)
        #pragma unroll
        for (int hf = 0; hf < 2; hf++) {
            lsum[mt][hf] += __shfl_xor_sync(0xffffffffu, lsum[mt][hf], 1);
            lsum[mt][hf] += __shfl_xor_sync(0xffffffffu, lsum[mt][hf], 2);
        }

    float* sO = (float*)(fb + FQB + warpM * (32*ORS*4));   // per-m scratch
    float* sL = (float*)(fb + FQB + 2*(32*ORS*4));         // 128 floats

    if (warpN == 1) {
        #pragma unroll
        for (int mt = 0; mt < 2; mt++) {
            #pragma unroll
            for (int nj = 0; nj < 8; nj++) {
                const float* d = oacc[mt*8 + nj];
                #pragma unroll
                for (int hf = 0; hf < 2; hf++) {
                    const int r = mt*16 + hf*8 + (l >> 2);
                    const int c = nj*8 + (l & 3)*2;
                    float2 v; v.x = d[hf*2 + 0]; v.y = d[hf*2 + 1];
                    *(float2*)&sO[r*ORS + c] = v;
                }
            }
        }
        if ((l & 3) == 0) {
            #pragma unroll
            for (int mt = 0; mt < 2; mt++)
                #pragma unroll
                for (int hf = 0; hf < 2; hf++)
                    sL[warpM*32 + mt*16 + hf*8 + (l >> 2)] = lsum[mt][hf];
        }
    }
    __syncthreads();

    if (warpN == 0) {
        const int bb = bh >> 4, hh = bh & 15;
        #pragma unroll
        for (int mt = 0; mt < 2; mt++) {
            float inv[2];
            #pragma unroll
            for (int hf = 0; hf < 2; hf++) {
                const float tot = lsum[mt][hf] + sL[warpM*32 + mt*16 + hf*8 + (l >> 2)];
                inv[hf] = 1.0f / tot;
            }
            #pragma unroll
            for (int nj = 0; nj < 8; nj++) {
                const float* d = oacc[mt*8 + nj];
                const int c = nj*8 + (l & 3)*2;
                #pragma unroll
                for (int hf = 0; hf < 2; hf++) {
                    const int rloc = mt*16 + hf*8 + (l >> 2);
                    float2 pv = *(float2*)&sO[rloc*ORS + c];
                    const float e0 = (d[hf*2 + 0] + pv.x) * inv[hf];
                    const float e1 = (d[hf*2 + 1] + pv.y) * inv[hf];
                    const int r = q0 + warpM*32 + rloc;
                    const int col = hh*HD + c;
                    *(__half2*)(g_a + (size_t)(bb*SS + r)*DM + col) =
                        __floats2half2_rn(e0, e1);
                }
            }
        }
    }
}

// ---------------------------------------------------------------------------
// host: tensor-map construction via driver entry point (no -lcuda needed)
// ---------------------------------------------------------------------------
typedef CUresult (CUDAAPI *PFN_encodeTiled)(
    CUtensorMap*, CUtensorMapDataType, cuuint32_t, void*,
    const cuuint64_t*, const cuuint64_t*, const cuuint32_t*, const cuuint32_t*,
    CUtensorMapInterleave, CUtensorMapSwizzle, CUtensorMapL2promotion,
    CUtensorMapFloatOOBfill);

static PFN_encodeTiled get_encoder() {
    static PFN_encodeTiled fn = nullptr;
    if (!fn) {
        void* p = nullptr;
        cudaDriverEntryPointQueryResult qr;
        cudaGetDriverEntryPoint("cuTensorMapEncodeTiled", &p, cudaEnableDefault, &qr);
        fn = (PFN_encodeTiled)p;
    }
    return fn;
}

static void mk2d(CUtensorMap* m, void* base, uint64_t d0, uint64_t rows,
                 uint32_t b0, uint32_t b1) {
    cuuint64_t dims[2]    = {d0, rows};
    cuuint64_t strides[1] = {d0 * 2};     // bytes
    cuuint32_t box[2]     = {b0, b1};
    cuuint32_t es[2]      = {1, 1};
    get_encoder()(m, CU_TENSOR_MAP_DATA_TYPE_FLOAT16, 2, base,
                  dims, strides, box, es,
                  CU_TENSOR_MAP_INTERLEAVE_NONE, CU_TENSOR_MAP_SWIZZLE_128B,
                  CU_TENSOR_MAP_L2_PROMOTION_L2_128B,
                  CU_TENSOR_MAP_FLOAT_OOB_FILL_NONE);
}

extern "C" void kernel_launch(void* const* d_in, const int* in_sizes, int n_in,
                              void* d_out, int out_size) {
    const float* x     = (const float*)d_in[0];
    const float* rel   = (const float*)d_in[1];
    const float* alpha = (const float*)d_in[2];
    const float* Wq    = (const float*)d_in[3];
    const float* bq    = (const float*)d_in[4];
    const float* Wk    = (const float*)d_in[5];
    const float* bk    = (const float*)d_in[6];
    const float* Wv    = (const float*)d_in[7];
    const float* bv    = (const float*)d_in[8];
    const float* Wo    = (const float*)d_in[9];
    const float* bo    = (const float*)d_in[10];
    float* out = (float*)d_out;

    cudaFuncSetAttribute(gemm_tma,  cudaFuncAttributeMaxDynamicSharedMemorySize, GEMM_SMEM);
    cudaFuncSetAttribute(flash_tma, cudaFuncAttributeMaxDynamicSharedMemorySize, FL_SMEM);

    void *a, *w, *qh, *kh, *vh;
    cudaGetSymbolAddress(&a,  g_a);
    cudaGetSymbolAddress(&w,  g_w);
    cudaGetSymbolAddress(&qh, g_qh);
    cudaGetSymbolAddress(&kh, g_kh);
    cudaGetSymbolAddress(&vh, g_vh);

    CUtensorMap mA, mW, mQh, mKh, mVh;
    mk2d(&mA,  a,  DM, MT,          64, 128);
    mk2d(&mW,  w,  DM, 4*DM,        64, 64);
    mk2d(&mQh, qh, HD, BB*NH*SS,    64, 64);
    mk2d(&mKh, kh, HD, BB*NH*SS,    64, 64);
    mk2d(&mVh, vh, HD, BB*NH*SS,    64, 64);

    pe_kernel<<<(MT*(DM/2) + 255)/256, 256>>>(x, rel, alpha);
    conv4_kernel<<<(4*NW4 + 255)/256, 256>>>(Wq, Wk, Wv, Wo);

    gemm_tma<<<dim3(3*DM/64, MT/128), 128, GEMM_SMEM>>>(
        mA, mW, bq, bk, bv, nullptr, 0, 0);

    flash_tma<<<dim3(SS/64, BB*NH), 128, FL_SMEM>>>(mQh, mKh, mVh);

    gemm_tma<<<dim3(DM/64, MT/128), 128, GEMM_SMEM>>>(
        mA, mW, bo, bo, bo, out, 3*DM, 3);
}